// round 14
// baseline (speedup 1.0000x reference)
#include <cuda_runtime.h>
#include <cuda_bf16.h>

typedef unsigned long long ull;

// ---------------- device scratch (no runtime allocation) ----------------
__device__ __nv_bfloat16 d_xb[(size_t)65536 * 256];  // gathered embeddings bf16 [m][256]
__device__ unsigned d_gx[(size_t)2 * 65536 * 512];   // input gate preacts bf16x2 [dir][m][512 pairs]
__device__ unsigned d_hcat[(size_t)128 * 512 * 256]; // bf16x2 [b][l][256 pairs] (hf|hb)
__device__ float d_emission[(size_t)65536 * 16];     // [b*512+l][16]
__device__ uint4 d_whh2[65536];                      // W_hh mma B fragments [dir][gate][w][kt][lane]
__device__ uint4 d_wih2[65536];                      // W_ih mma B fragments [dir][nt16][kt][lane]
__device__ double d_acc[2];                          // [all_path, golden]

// ---------------- helpers ----------------
__device__ __forceinline__ float bflo(unsigned w) { return __uint_as_float(w << 16); }
__device__ __forceinline__ float bfhi(unsigned w) { return __uint_as_float(w & 0xffff0000u); }
__device__ __forceinline__ float bfhalf(unsigned u, int hi) {
    return __uint_as_float(hi ? (u & 0xffff0000u) : (u << 16));
}
__device__ __forceinline__ float tanha(float x) {
    float r; asm("tanh.approx.f32 %0,%1;" : "=f"(r) : "f"(x)); return r;
}
__device__ __forceinline__ float sigt(float x) { return fmaf(tanha(0.5f * x), 0.5f, 0.5f); }

__device__ __forceinline__ unsigned smem_u32(const void* p) {
    unsigned a;
    asm("{ .reg .u64 t; cvta.to.shared.u64 t, %1; cvt.u32.u64 %0, t; }" : "=r"(a) : "l"(p));
    return a;
}
__device__ __forceinline__ unsigned mapa_u32(unsigned a, unsigned rank) {
    unsigned d; asm("mapa.shared::cluster.u32 %0,%1,%2;" : "=r"(d) : "r"(a), "r"(rank));
    return d;
}
__device__ __forceinline__ unsigned cvt_bf2(float hi, float lo) {
    unsigned u; asm("cvt.rn.bf16x2.f32 %0,%1,%2;" : "=r"(u) : "f"(hi), "f"(lo)); return u;
}

#define MMA_BF16(C, A, B0, B1)                                                          \
    asm volatile("mma.sync.aligned.m16n8k16.row.col.f32.bf16.bf16.f32 "                 \
                 "{%0,%1,%2,%3},{%4,%5,%6,%7},{%8,%9},{%0,%1,%2,%3};"                   \
                 : "+f"((C)[0]), "+f"((C)[1]), "+f"((C)[2]), "+f"((C)[3])               \
                 : "r"((A)[0]), "r"((A)[1]), "r"((A)[2]), "r"((A)[3]),                  \
                   "r"(B0), "r"(B1))
#define LDSM4(R, ADDR)                                                                  \
    asm volatile("ldmatrix.sync.aligned.m8n8.x4.shared.b16 {%0,%1,%2,%3},[%4];"         \
                 : "=r"((R)[0]), "=r"((R)[1]), "=r"((R)[2]), "=r"((R)[3]) : "r"(ADDR))

#define MBAR_WAIT(ADDR, PH)                                                             \
    do {                                                                                \
        unsigned done;                                                                  \
        asm volatile("{\n\t.reg .pred p;\n\t"                                           \
                     "mbarrier.try_wait.parity.acquire.cluster.shared::cta.b64 p, [%1], %2;\n\t" \
                     "selp.b32 %0, 1, 0, p;\n\t}"                                       \
                     : "=r"(done) : "r"(ADDR), "r"(PH) : "memory");                     \
        while (!done)                                                                   \
            asm volatile("{\n\t.reg .pred p;\n\t"                                       \
                         "mbarrier.try_wait.parity.acquire.cluster.shared::cta.b64 p, [%1], %2, 0x989680;\n\t" \
                         "selp.b32 %0, 1, 0, p;\n\t}"                                   \
                         : "=r"(done) : "r"(ADDR), "r"(PH) : "memory");                 \
    } while (0)

// ---------------- K0: prep (whh + wih fragments, zero acc) ----------------
__device__ __forceinline__ unsigned pkbf(const float* s, int n, int k) {
    unsigned short lo = __bfloat16_as_ushort(__float2bfloat16(s[n * 256 + k]));
    unsigned short hi = __bfloat16_as_ushort(__float2bfloat16(s[n * 256 + k + 1]));
    return ((unsigned)hi << 16) | (unsigned)lo;
}
__global__ void k_prep(const float* __restrict__ whf, const float* __restrict__ whb,
                       const float* __restrict__ wif, const float* __restrict__ wib) {
    int e = blockIdx.x * 256 + threadIdx.x;   // 0..131071
    if (e < 65536) {
        int lane = e & 31, kt = (e >> 5) & 15, w = (e >> 9) & 15;
        int g = (e >> 13) & 3, dir = (e >> 15) & 1;
        const float* src = dir ? whb : whf;
        int row = g * 256 + w * 16 + (lane >> 2);
        int k0 = kt * 16 + (lane & 3) * 2;
        uint4 v;
        v.x = pkbf(src, row, k0);     v.y = pkbf(src, row, k0 + 8);
        v.z = pkbf(src, row + 8, k0); v.w = pkbf(src, row + 8, k0 + 8);
        d_whh2[e] = v;
    } else {
        int f = e - 65536;
        int lane = f & 31, kt = (f >> 5) & 15, nt = (f >> 9) & 63, dir = (f >> 15) & 1;
        const float* src = dir ? wib : wif;
        int row = nt * 16 + (lane >> 2);
        int k0 = kt * 16 + (lane & 3) * 2;
        uint4 v;
        v.x = pkbf(src, row, k0);     v.y = pkbf(src, row, k0 + 8);
        v.z = pkbf(src, row + 8, k0); v.w = pkbf(src, row + 8, k0 + 8);
        d_wih2[f] = v;
    }
    if (e < 2) d_acc[e] = 0.0;
}

// ---------------- K1a: embedding gather (fp32 -> bf16) ----------------
__global__ void k_gather(const int* __restrict__ bd, const float* __restrict__ emb) {
    int m = blockIdx.x * 8 + (threadIdx.x >> 5);
    int lane = threadIdx.x & 31;
    int b = m & 127, l = m >> 7;
    int idx = bd[b * 512 + l];
    const float* src = emb + (size_t)idx * 256;
    unsigned* dst = (unsigned*)(d_xb + (size_t)m * 256);
#pragma unroll
    for (int t = 0; t < 4; t++) {
        int i = lane + t * 32;
        float2 v = *(const float2*)(src + 2 * i);
        dst[i] = cvt_bf2(v.y, v.x);
    }
}

// ---------------- K1b: input projection via mma.sync bf16, B staged in smem ----------------
#define GSM 133120
__global__ void __launch_bounds__(256) k_gemm(const float* __restrict__ bf_,
                                              const float* __restrict__ bb_) {
    extern __shared__ char sm[];
    uint4* Bs = (uint4*)(sm + 67584);
    int tid = threadIdx.x, lane = tid & 31, w = tid >> 5;
    int m0 = blockIdx.x * 128;
    int n0 = blockIdx.y * 128;
    int dir = n0 >> 10, nloc = n0 & 1023;

    // stage A tile 128 x 256 bf16 (pitch 528B -> conflict-free ldmatrix)
    for (int i = tid; i < 4096; i += 256) {
        int r = i >> 5, c = i & 31;
        ((uint4*)(sm + r * 528))[c] = ((const uint4*)(d_xb + (size_t)(m0 + r) * 256))[c];
    }
    // stage B slice: 8 nt16 fragment blocks = 4096 contiguous uint4 (64 KB)
    const uint4* Bg = d_wih2 + ((size_t)dir * 64 + (nloc >> 4)) * 512;
    for (int i = tid; i < 4096; i += 256) Bs[i] = Bg[i];
    __syncthreads();

    float c[16][4];
#pragma unroll
    for (int t = 0; t < 16; t++)
#pragma unroll
        for (int r = 0; r < 4; r++) c[t][r] = 0.f;

    unsigned ab = smem_u32(sm) + (unsigned)(w * 16 + (lane & 15)) * 528 + ((unsigned)(lane >> 4) << 4);
#pragma unroll
    for (int kt = 0; kt < 16; kt++) {
        unsigned a[4];
        LDSM4(a, ab + (unsigned)kt * 32);
#pragma unroll
        for (int p = 0; p < 8; p++) {
            uint4 bq = Bs[p * 512 + kt * 32 + lane];
            MMA_BF16(c[2 * p], a, bq.x, bq.y);
            MMA_BF16(c[2 * p + 1], a, bq.z, bq.w);
        }
    }
    const float* Bv = dir ? bb_ : bf_;
    int mrow = m0 + w * 16 + (lane >> 2);
    unsigned* gbase = d_gx + ((size_t)dir * 65536 + mrow) * 512 + (nloc >> 1) + (lane & 3);
#pragma unroll
    for (int nt = 0; nt < 16; nt++) {
        float2 bv = *(const float2*)(Bv + nloc + nt * 8 + (lane & 3) * 2);
        gbase[nt * 4] = cvt_bf2(c[nt][1] + bv.y, c[nt][0] + bv.x);
        gbase[8 * 512 + nt * 4] = cvt_bf2(c[nt][3] + bv.y, c[nt][2] + bv.x);
    }
}

// ---------------- K2: LSTM recurrence, cluster-of-4 gate-split (R9 protocol) ----------------
#define HPITCH   528
#define HBUFB    8448
#define OFF_H    0                       // h bufs [0, 16896)
#define OFF_RECV 16896                   // 4 KB: [gate][q][128 pairs]
#define OFF_MBAR 20992
#define SMEM_R   21008

__global__ void __launch_bounds__(512, 1) __cluster_dims__(4, 1, 1) k_recur() {
    extern __shared__ char sm[];
    int tid = threadIdx.x;
    unsigned rank;
    asm("mov.u32 %0, %%cluster_ctarank;" : "=r"(rank));
    int cid = blockIdx.x >> 2;
    int dir = cid >> 4;
    int b0 = (cid & 15) * 8;
    int lane = tid & 31, w = tid >> 5;

    // this warp's weight fragments (16 kt x uint4) -> registers, once
    const uint4* wgp = d_whh2 + (size_t)(dir * 4 + (int)rank) * 8192 + w * 512 + lane;
    uint4 wreg[16];
#pragma unroll
    for (int kt = 0; kt < 16; kt++) wreg[kt] = wgp[kt * 32];

    for (int i = tid; i < 2 * HBUFB / 4; i += 512) ((unsigned*)(sm + OFF_H))[i] = 0u;

    ull* mbar = (ull*)(sm + OFF_MBAR);
    if (tid == 0) {
        asm volatile("mbarrier.init.shared.b64 [%0], 3;" :: "r"(smem_u32(&mbar[0])) : "memory");
        asm volatile("mbarrier.init.shared.b64 [%0], 3;" :: "r"(smem_u32(&mbar[1])) : "memory");
    }
    __syncthreads();
    asm volatile("barrier.cluster.arrive.aligned;" ::: "memory");
    asm volatile("barrier.cluster.wait.aligned;" ::: "memory");

    unsigned rv_l = smem_u32(sm + OFF_RECV);
    unsigned h_l  = smem_u32(sm + OFF_H);
    unsigned b1_l = smem_u32(&mbar[0]);
    unsigned b2_l = smem_u32(&mbar[1]);
    unsigned rh[4], rb1[4], rb2[4];
#pragma unroll
    for (int r = 0; r < 4; r++) {
        rh[r]  = mapa_u32(h_l, r);
        rb1[r] = mapa_u32(b1_l, r);
        rb2[r] = mapa_u32(b2_l, r);
    }

    // producer roles: this CTA computes gate `rank` for 8 batch rows
    unsigned abase0 = h_l + (unsigned)(lane & 15) * HPITCH + ((unsigned)(lane >> 4) << 4);
    int bE = lane >> 2;
    unsigned rdst = (unsigned)(bE >> 1);
    int qE = bE & 1;
    int nl = w * 16 + (lane & 3) * 2;
    unsigned dst0 = mapa_u32(rv_l, rdst) + ((unsigned)rank * 256 + qE * 128 + (nl >> 1)) * 4;

    // consumer roles: cell update for own 2 batch rows
    int q = tid >> 8, j = tid & 255;
    int b_own = b0 + (int)rank * 2 + q;
    int hrow = (int)rank * 2 + q;
    const unsigned* rcv = (const unsigned*)(sm + OFF_RECV) + q * 128 + (j >> 1);
    int hlf = j & 1;

    float cc = 0.f;
    const unsigned* gxb = d_gx + (size_t)dir * 65536 * 512;
    int buf = 0;

    // producer gx prefetch (gate `rank` slice for batch bE), bf16x2 pairs
    int gxoff = (int)rank * 128 + (nl >> 1);
    int l0 = dir ? 511 : 0;
    const unsigned* gxp = gxb + (size_t)(l0 * 128 + b0 + bE) * 512 + gxoff;
    unsigned ga_u = gxp[0], gb_u = gxp[4];

    for (int step = 0; step < 512; step++) {
        int l = dir ? (511 - step) : step;

        // ---- matvec: this gate's 256 preacts for 8 batches (weights in regs) ----
        float c0[4] = {0.f, 0.f, 0.f, 0.f}, c1[4] = {0.f, 0.f, 0.f, 0.f};
        unsigned ab = abase0 + (unsigned)buf * HBUFB;
#pragma unroll
        for (int kt = 0; kt < 16; kt++) {
            unsigned a[4];
            LDSM4(a, ab + (unsigned)kt * 32);
            MMA_BF16(c0, a, wreg[kt].x, wreg[kt].y);
            MMA_BF16(c1, a, wreg[kt].z, wreg[kt].w);
        }
        // ship complete preacts (matvec + gx) to owner CTA
        unsigned u0 = cvt_bf2(c0[1] + bfhi(ga_u), c0[0] + bflo(ga_u));
        unsigned u1 = cvt_bf2(c1[1] + bfhi(gb_u), c1[0] + bflo(gb_u));
        asm volatile("st.shared::cluster.u32 [%0],%1;" :: "r"(dst0), "r"(u0) : "memory");
        asm volatile("st.shared::cluster.u32 [%0],%1;" :: "r"(dst0 + 16), "r"(u1) : "memory");
        __syncthreads();
        if (tid == 0) {
#pragma unroll
            for (int r = 0; r < 4; r++)
                if (r != (int)rank)
                    asm volatile("mbarrier.arrive.release.cluster.shared::cluster.b64 _, [%0];"
                                 :: "r"(rb1[r]) : "memory");
        }
        {
            unsigned ph = (unsigned)step & 1u;
            MBAR_WAIT(b1_l, ph);
        }

        // ---- cell update for own 2 batch rows (preacts already include gx) ----
        float pi = bfhalf(rcv[0],   hlf);
        float pf = bfhalf(rcv[256], hlf);
        float pg = bfhalf(rcv[512], hlf);
        float po = bfhalf(rcv[768], hlf);
        float i_ = sigt(pi), f_ = sigt(pf), g_ = tanha(pg), o_ = sigt(po);
        cc = f_ * cc + i_ * g_;
        float hv = o_ * tanha(cc);

        // ---- broadcast new h row to all 4 CTAs + bf16x2 hcat store ----
        float hn = __shfl_down_sync(0xffffffffu, hv, 1);
        if (!hlf) {
            unsigned hu = cvt_bf2(hn, hv);
            unsigned off = (unsigned)(buf ^ 1) * HBUFB + (unsigned)hrow * HPITCH + (unsigned)j * 2;
#pragma unroll
            for (int r = 0; r < 4; r++)
                asm volatile("st.shared::cluster.u32 [%0],%1;" :: "r"(rh[r] + off), "r"(hu) : "memory");
            d_hcat[((size_t)b_own * 512 + l) * 256 + dir * 128 + (j >> 1)] = hu;
        }
        __syncthreads();
        if (tid == 0) {
#pragma unroll
            for (int r = 0; r < 4; r++)
                if (r != (int)rank)
                    asm volatile("mbarrier.arrive.release.cluster.shared::cluster.b64 _, [%0];"
                                 :: "r"(rb2[r]) : "memory");
        }
        // producer gx prefetch for next step (into wait-2 shadow)
        if (step < 511) {
            int ln = dir ? (510 - step) : (step + 1);
            gxp = gxb + (size_t)(ln * 128 + b0 + bE) * 512 + gxoff;
            ga_u = gxp[0];
            gb_u = gxp[4];
        }
        {
            unsigned ph = (unsigned)step & 1u;
            MBAR_WAIT(b2_l, ph);
        }
        buf ^= 1;
    }

    asm volatile("barrier.cluster.arrive.aligned;" ::: "memory");
    asm volatile("barrier.cluster.wait.aligned;" ::: "memory");
}

// ---------------- K3: emission = hcat(bf16) @ w_cls^T + b_cls ----------------
__global__ void __launch_bounds__(256) k_emis(const float* __restrict__ wcls,
                                              const float* __restrict__ bcls) {
    __shared__ float wc[16 * 512];
    int tid = threadIdx.x;
    for (int i = tid; i < 16 * 512 / 4; i += 256)
        ((float4*)wc)[i] = ((const float4*)wcls)[i];
    __syncthreads();
    int m = blockIdx.x * 8 + (tid >> 5);
    int lane = tid & 31;
    float acc[16];
#pragma unroll
    for (int t = 0; t < 16; t++) acc[t] = 0.f;
    const unsigned* hp = d_hcat + (size_t)m * 256;
#pragma unroll
    for (int it = 0; it < 8; it++) {
        int m32 = it * 32 + lane;
        unsigned u = hp[m32];
        float h0 = bflo(u), h1 = bfhi(u);
#pragma unroll
        for (int t = 0; t < 16; t++)
            acc[t] += h0 * wc[t * 512 + 2 * m32] + h1 * wc[t * 512 + 2 * m32 + 1];
    }
#pragma unroll
    for (int t = 0; t < 16; t++)
#pragma unroll
        for (int off = 16; off; off >>= 1) acc[t] += __shfl_xor_sync(0xffffffffu, acc[t], off);
    if (lane < 16) {
        float v = acc[0];
#pragma unroll
        for (int t = 1; t < 16; t++) v = (lane == t) ? acc[t] : v;
        d_emission[(size_t)m * 16 + lane] = v + bcls[lane];
    }
}

// ---------------- K4: CRF golden + forward (1 warp / batch row) ----------------
__global__ void k_crf(const int* __restrict__ tag, const float* __restrict__ trans) {
    __shared__ float tr[256];
    int b = blockIdx.x, lane = threadIdx.x;
    for (int i = lane; i < 256; i += 32) tr[i] = trans[i];
    __syncwarp();
    int cur = lane & 15;
    float tcol[16];
#pragma unroll
    for (int p = 0; p < 16; p++) tcol[p] = tr[p * 16 + cur];
    const int* tg = tag + b * 512;
    int len = 0;
    for (int l2 = lane; l2 < 512; l2 += 32) len += (tg[l2] != 0);
#pragma unroll
    for (int off = 16; off; off >>= 1) len += __shfl_xor_sync(0xffffffffu, len, off);

    const float* em = d_emission + (size_t)b * 512 * 16;
    float gsum = 0.f;
    for (int l2 = lane; l2 < 512; l2 += 32)
        if (l2 < len) {
            int t = tg[l2];
            int pv = l2 ? tg[l2 - 1] : 14;       // START=14
            gsum += em[l2 * 16 + t] + tr[pv * 16 + t];
        }
#pragma unroll
    for (int off = 16; off; off >>= 1) gsum += __shfl_xor_sync(0xffffffffu, gsum, off);

    float score = em[cur] + tr[14 * 16 + cur];
    for (int t = 1; t < 512; t++) {
        float v[16];
#pragma unroll
        for (int p = 0; p < 16; p++)
            v[p] = __shfl_sync(0xffffffffu, score, p) + tcol[p];
        float m0 = fmaxf(fmaxf(v[0], v[1]), fmaxf(v[2], v[3]));
        float m1 = fmaxf(fmaxf(v[4], v[5]), fmaxf(v[6], v[7]));
        float m2 = fmaxf(fmaxf(v[8], v[9]), fmaxf(v[10], v[11]));
        float m3 = fmaxf(fmaxf(v[12], v[13]), fmaxf(v[14], v[15]));
        float m = fmaxf(fmaxf(m0, m1), fmaxf(m2, m3));
        float e[16];
#pragma unroll
        for (int p = 0; p < 16; p++) e[p] = __expf(v[p] - m);
        float s0 = (e[0] + e[1]) + (e[2] + e[3]);
        float s1 = (e[4] + e[5]) + (e[6] + e[7]);
        float s2 = (e[8] + e[9]) + (e[10] + e[11]);
        float s3 = (e[12] + e[13]) + (e[14] + e[15]);
        float s = (s0 + s1) + (s2 + s3);
        float ns = em[t * 16 + cur] + m + __logf(s);
        score = (t < len) ? ns : score;
    }
    if (lane == 15) atomicAdd(&d_acc[0], (double)score);  // END=15
    if (lane == 0)  atomicAdd(&d_acc[1], (double)gsum);
}

__global__ void k_final(float* out) {
    out[0] = (float)((d_acc[0] - d_acc[1]) / 128.0);
}

// ---------------- launch ----------------
extern "C" void kernel_launch(void* const* d_in, const int* in_sizes, int n_in,
                              void* d_out, int out_size) {
    const int*   batch_data = (const int*)d_in[0];
    const int*   batch_tag  = (const int*)d_in[1];
    const float* emb        = (const float*)d_in[2];
    const float* w_ih_f     = (const float*)d_in[3];
    const float* w_hh_f     = (const float*)d_in[4];
    const float* b_f        = (const float*)d_in[5];
    const float* w_ih_b     = (const float*)d_in[6];
    const float* w_hh_b     = (const float*)d_in[7];
    const float* b_b        = (const float*)d_in[8];
    const float* w_cls      = (const float*)d_in[9];
    const float* b_cls      = (const float*)d_in[10];
    const float* transition = (const float*)d_in[11];

    cudaFuncSetAttribute(k_recur, cudaFuncAttributeMaxDynamicSharedMemorySize, SMEM_R);
    cudaFuncSetAttribute(k_gemm, cudaFuncAttributeMaxDynamicSharedMemorySize, GSM);

    k_prep<<<512, 256>>>(w_hh_f, w_hh_b, w_ih_f, w_ih_b);
    k_gather<<<8192, 256>>>(batch_data, emb);
    k_gemm<<<dim3(512, 16), 256, GSM>>>(b_f, b_b);
    k_recur<<<128, 512, SMEM_R>>>();
    k_emis<<<8192, 256>>>(w_cls, b_cls);
    k_crf<<<128, 32>>>(batch_tag, transition);
    k_final<<<1, 1>>>((float*)d_out);
}

// round 15
// speedup vs baseline: 1.0502x; 1.0502x over previous
#include <cuda_runtime.h>
#include <cuda_bf16.h>

typedef unsigned long long ull;

// ---------------- device scratch (no runtime allocation) ----------------
__device__ __nv_bfloat16 d_xb[(size_t)65536 * 256];  // gathered embeddings bf16 [m][256]
__device__ unsigned d_gx[(size_t)2 * 65536 * 512];   // input gate preacts bf16x2 [dir][m][512 pairs]
__device__ unsigned d_hcat[(size_t)128 * 512 * 256]; // bf16x2 [b][l][256 pairs] (hf|hb)
__device__ float d_emission[(size_t)65536 * 16];     // [b*512+l][16]
__device__ uint4 d_whh2[65536];                      // W_hh mma B fragments [dir][gate][w][kt][lane]
__device__ uint4 d_wih2[65536];                      // W_ih mma B fragments [dir][nt16][kt][lane]
__device__ double d_acc[2];                          // [all_path, golden]

// ---------------- helpers ----------------
__device__ __forceinline__ float bflo(unsigned w) { return __uint_as_float(w << 16); }
__device__ __forceinline__ float bfhi(unsigned w) { return __uint_as_float(w & 0xffff0000u); }
__device__ __forceinline__ float bfhalf(unsigned u, int hi) {
    return __uint_as_float(hi ? (u & 0xffff0000u) : (u << 16));
}
__device__ __forceinline__ float tanha(float x) {
    float r; asm("tanh.approx.f32 %0,%1;" : "=f"(r) : "f"(x)); return r;
}
__device__ __forceinline__ float sigt(float x) { return fmaf(tanha(0.5f * x), 0.5f, 0.5f); }

__device__ __forceinline__ unsigned smem_u32(const void* p) {
    unsigned a;
    asm("{ .reg .u64 t; cvta.to.shared.u64 t, %1; cvt.u32.u64 %0, t; }" : "=r"(a) : "l"(p));
    return a;
}
__device__ __forceinline__ unsigned mapa_u32(unsigned a, unsigned rank) {
    unsigned d; asm("mapa.shared::cluster.u32 %0,%1,%2;" : "=r"(d) : "r"(a), "r"(rank));
    return d;
}
__device__ __forceinline__ unsigned cvt_bf2(float hi, float lo) {
    unsigned u; asm("cvt.rn.bf16x2.f32 %0,%1,%2;" : "=r"(u) : "f"(hi), "f"(lo)); return u;
}

#define MMA_BF16(C, A, B0, B1)                                                          \
    asm volatile("mma.sync.aligned.m16n8k16.row.col.f32.bf16.bf16.f32 "                 \
                 "{%0,%1,%2,%3},{%4,%5,%6,%7},{%8,%9},{%0,%1,%2,%3};"                   \
                 : "+f"((C)[0]), "+f"((C)[1]), "+f"((C)[2]), "+f"((C)[3])               \
                 : "r"((A)[0]), "r"((A)[1]), "r"((A)[2]), "r"((A)[3]),                  \
                   "r"(B0), "r"(B1))
#define LDSM4(R, ADDR)                                                                  \
    asm volatile("ldmatrix.sync.aligned.m8n8.x4.shared.b16 {%0,%1,%2,%3},[%4];"         \
                 : "=r"((R)[0]), "=r"((R)[1]), "=r"((R)[2]), "=r"((R)[3]) : "r"(ADDR))

#define MBAR_WAIT(ADDR, PH)                                                             \
    do {                                                                                \
        unsigned done;                                                                  \
        asm volatile("{\n\t.reg .pred p;\n\t"                                           \
                     "mbarrier.try_wait.parity.acquire.cluster.shared::cta.b64 p, [%1], %2;\n\t" \
                     "selp.b32 %0, 1, 0, p;\n\t}"                                       \
                     : "=r"(done) : "r"(ADDR), "r"(PH) : "memory");                     \
        while (!done)                                                                   \
            asm volatile("{\n\t.reg .pred p;\n\t"                                       \
                         "mbarrier.try_wait.parity.acquire.cluster.shared::cta.b64 p, [%1], %2, 0x989680;\n\t" \
                         "selp.b32 %0, 1, 0, p;\n\t}"                                   \
                         : "=r"(done) : "r"(ADDR), "r"(PH) : "memory");                 \
    } while (0)

// ---------------- K0: prep (whh + wih fragments, zero acc) ----------------
__device__ __forceinline__ unsigned pkbf(const float* s, int n, int k) {
    unsigned short lo = __bfloat16_as_ushort(__float2bfloat16(s[n * 256 + k]));
    unsigned short hi = __bfloat16_as_ushort(__float2bfloat16(s[n * 256 + k + 1]));
    return ((unsigned)hi << 16) | (unsigned)lo;
}
__global__ void k_prep(const float* __restrict__ whf, const float* __restrict__ whb,
                       const float* __restrict__ wif, const float* __restrict__ wib) {
    int e = blockIdx.x * 256 + threadIdx.x;   // 0..131071
    if (e < 65536) {
        int lane = e & 31, kt = (e >> 5) & 15, w = (e >> 9) & 15;
        int g = (e >> 13) & 3, dir = (e >> 15) & 1;
        const float* src = dir ? whb : whf;
        int row = g * 256 + w * 16 + (lane >> 2);
        int k0 = kt * 16 + (lane & 3) * 2;
        uint4 v;
        v.x = pkbf(src, row, k0);     v.y = pkbf(src, row, k0 + 8);
        v.z = pkbf(src, row + 8, k0); v.w = pkbf(src, row + 8, k0 + 8);
        d_whh2[e] = v;
    } else {
        int f = e - 65536;
        int lane = f & 31, kt = (f >> 5) & 15, nt = (f >> 9) & 63, dir = (f >> 15) & 1;
        const float* src = dir ? wib : wif;
        int row = nt * 16 + (lane >> 2);
        int k0 = kt * 16 + (lane & 3) * 2;
        uint4 v;
        v.x = pkbf(src, row, k0);     v.y = pkbf(src, row, k0 + 8);
        v.z = pkbf(src, row + 8, k0); v.w = pkbf(src, row + 8, k0 + 8);
        d_wih2[f] = v;
    }
    if (e < 2) d_acc[e] = 0.0;
}

// ---------------- K1a: embedding gather (fp32 -> bf16) ----------------
__global__ void k_gather(const int* __restrict__ bd, const float* __restrict__ emb) {
    int m = blockIdx.x * 8 + (threadIdx.x >> 5);
    int lane = threadIdx.x & 31;
    int b = m & 127, l = m >> 7;
    int idx = bd[b * 512 + l];
    const float* src = emb + (size_t)idx * 256;
    unsigned* dst = (unsigned*)(d_xb + (size_t)m * 256);
#pragma unroll
    for (int t = 0; t < 4; t++) {
        int i = lane + t * 32;
        float2 v = *(const float2*)(src + 2 * i);
        dst[i] = cvt_bf2(v.y, v.x);
    }
}

// ---------------- K1b: input projection via mma.sync bf16, bf16x2 gx out ----------------
#define GSM 67584
__global__ void __launch_bounds__(256) k_gemm(const float* __restrict__ bf_,
                                              const float* __restrict__ bb_) {
    extern __shared__ char sm[];
    int tid = threadIdx.x, lane = tid & 31, w = tid >> 5;
    int m0 = blockIdx.x * 128;
    int n0 = blockIdx.y * 128;
    int dir = n0 >> 10, nloc = n0 & 1023;

    for (int i = tid; i < 4096; i += 256) {
        int r = i >> 5, c = i & 31;
        ((uint4*)(sm + r * 528))[c] = ((const uint4*)(d_xb + (size_t)(m0 + r) * 256))[c];
    }
    __syncthreads();

    const uint4* Bp = d_wih2 + ((size_t)dir * 64 + (nloc >> 4)) * 512 + lane;
    float c[16][4];
#pragma unroll
    for (int t = 0; t < 16; t++)
#pragma unroll
        for (int r = 0; r < 4; r++) c[t][r] = 0.f;

    unsigned ab = smem_u32(sm) + (unsigned)(w * 16 + (lane & 15)) * 528 + ((unsigned)(lane >> 4) << 4);
#pragma unroll
    for (int kt = 0; kt < 16; kt++) {
        unsigned a[4];
        LDSM4(a, ab + (unsigned)kt * 32);
#pragma unroll
        for (int p = 0; p < 8; p++) {
            uint4 bq = Bp[p * 512 + kt * 32];
            MMA_BF16(c[2 * p], a, bq.x, bq.y);
            MMA_BF16(c[2 * p + 1], a, bq.z, bq.w);
        }
    }
    const float* Bv = dir ? bb_ : bf_;
    int mrow = m0 + w * 16 + (lane >> 2);
    unsigned* gbase = d_gx + ((size_t)dir * 65536 + mrow) * 512 + (nloc >> 1) + (lane & 3);
#pragma unroll
    for (int nt = 0; nt < 16; nt++) {
        float2 bv = *(const float2*)(Bv + nloc + nt * 8 + (lane & 3) * 2);
        gbase[nt * 4] = cvt_bf2(c[nt][1] + bv.y, c[nt][0] + bv.x);
        gbase[8 * 512 + nt * 4] = cvt_bf2(c[nt][3] + bv.y, c[nt][2] + bv.x);
    }
}

// ---------------- K2: LSTM recurrence, cluster-of-4 gate-split (R12 = best) ----------------
#define HPITCH   528
#define HBUFB    8448
#define OFF_H    0                       // h bufs [0, 16896)
#define OFF_RECV 16896                   // 4 KB: [gate][q][128 pairs]
#define OFF_MBAR 20992
#define SMEM_R   21008

__global__ void __launch_bounds__(512, 1) __cluster_dims__(4, 1, 1) k_recur() {
    extern __shared__ char sm[];
    int tid = threadIdx.x;
    unsigned rank;
    asm("mov.u32 %0, %%cluster_ctarank;" : "=r"(rank));
    int cid = blockIdx.x >> 2;
    int dir = cid >> 4;
    int b0 = (cid & 15) * 8;
    int lane = tid & 31, w = tid >> 5;

    // this warp's weight fragments (16 kt x uint4) -> registers, once
    const uint4* wgp = d_whh2 + (size_t)(dir * 4 + (int)rank) * 8192 + w * 512 + lane;
    uint4 wreg[16];
#pragma unroll
    for (int kt = 0; kt < 16; kt++) wreg[kt] = wgp[kt * 32];

    for (int i = tid; i < 2 * HBUFB / 4; i += 512) ((unsigned*)(sm + OFF_H))[i] = 0u;

    ull* mbar = (ull*)(sm + OFF_MBAR);
    if (tid == 0) {
        asm volatile("mbarrier.init.shared.b64 [%0], 3;" :: "r"(smem_u32(&mbar[0])) : "memory");
        asm volatile("mbarrier.init.shared.b64 [%0], 3;" :: "r"(smem_u32(&mbar[1])) : "memory");
    }
    __syncthreads();
    asm volatile("barrier.cluster.arrive.aligned;" ::: "memory");
    asm volatile("barrier.cluster.wait.aligned;" ::: "memory");

    unsigned rv_l = smem_u32(sm + OFF_RECV);
    unsigned h_l  = smem_u32(sm + OFF_H);
    unsigned b1_l = smem_u32(&mbar[0]);
    unsigned b2_l = smem_u32(&mbar[1]);
    unsigned rh[4], rb1[4], rb2[4];
#pragma unroll
    for (int r = 0; r < 4; r++) {
        rh[r]  = mapa_u32(h_l, r);
        rb1[r] = mapa_u32(b1_l, r);
        rb2[r] = mapa_u32(b2_l, r);
    }

    // producer roles: this CTA computes gate `rank` for 8 batch rows
    unsigned abase0 = h_l + (unsigned)(lane & 15) * HPITCH + ((unsigned)(lane >> 4) << 4);
    int bE = lane >> 2;
    unsigned rdst = (unsigned)(bE >> 1);
    int qE = bE & 1;
    int nl = w * 16 + (lane & 3) * 2;
    unsigned dst0 = mapa_u32(rv_l, rdst) + ((unsigned)rank * 256 + qE * 128 + (nl >> 1)) * 4;

    // consumer roles: cell update for own 2 batch rows
    int q = tid >> 8, j = tid & 255;
    int b_own = b0 + (int)rank * 2 + q;
    int hrow = (int)rank * 2 + q;
    const unsigned* rcv = (const unsigned*)(sm + OFF_RECV) + q * 128 + (j >> 1);
    int hlf = j & 1;

    float cc = 0.f;
    const unsigned* gxb = d_gx + (size_t)dir * 65536 * 512;
    int buf = 0;

    // producer gx prefetch (gate `rank` slice for batch bE), bf16x2 pairs
    int gxoff = (int)rank * 128 + (nl >> 1);
    int l0 = dir ? 511 : 0;
    const unsigned* gxp = gxb + (size_t)(l0 * 128 + b0 + bE) * 512 + gxoff;
    unsigned ga_u = gxp[0], gb_u = gxp[4];

    for (int step = 0; step < 512; step++) {
        int l = dir ? (511 - step) : step;

        // ---- matvec: this gate's 256 preacts for 8 batches (weights in regs) ----
        float c0[4] = {0.f, 0.f, 0.f, 0.f}, c1[4] = {0.f, 0.f, 0.f, 0.f};
        unsigned ab = abase0 + (unsigned)buf * HBUFB;
#pragma unroll
        for (int kt = 0; kt < 16; kt++) {
            unsigned a[4];
            LDSM4(a, ab + (unsigned)kt * 32);
            MMA_BF16(c0, a, wreg[kt].x, wreg[kt].y);
            MMA_BF16(c1, a, wreg[kt].z, wreg[kt].w);
        }
        // ship complete preacts (matvec + gx) to owner CTA
        unsigned u0 = cvt_bf2(c0[1] + bfhi(ga_u), c0[0] + bflo(ga_u));
        unsigned u1 = cvt_bf2(c1[1] + bfhi(gb_u), c1[0] + bflo(gb_u));
        asm volatile("st.shared::cluster.u32 [%0],%1;" :: "r"(dst0), "r"(u0) : "memory");
        asm volatile("st.shared::cluster.u32 [%0],%1;" :: "r"(dst0 + 16), "r"(u1) : "memory");
        __syncthreads();
        if (tid == 0) {
#pragma unroll
            for (int r = 0; r < 4; r++)
                if (r != (int)rank)
                    asm volatile("mbarrier.arrive.release.cluster.shared::cluster.b64 _, [%0];"
                                 :: "r"(rb1[r]) : "memory");
        }
        {
            unsigned ph = (unsigned)step & 1u;
            MBAR_WAIT(b1_l, ph);
        }

        // ---- cell update for own 2 batch rows (preacts already include gx) ----
        float pi = bfhalf(rcv[0],   hlf);
        float pf = bfhalf(rcv[256], hlf);
        float pg = bfhalf(rcv[512], hlf);
        float po = bfhalf(rcv[768], hlf);
        float i_ = sigt(pi), f_ = sigt(pf), g_ = tanha(pg), o_ = sigt(po);
        cc = f_ * cc + i_ * g_;
        float hv = o_ * tanha(cc);

        // ---- broadcast new h row to all 4 CTAs + bf16x2 hcat store ----
        float hn = __shfl_down_sync(0xffffffffu, hv, 1);
        if (!hlf) {
            unsigned hu = cvt_bf2(hn, hv);
            unsigned off = (unsigned)(buf ^ 1) * HBUFB + (unsigned)hrow * HPITCH + (unsigned)j * 2;
#pragma unroll
            for (int r = 0; r < 4; r++)
                asm volatile("st.shared::cluster.u32 [%0],%1;" :: "r"(rh[r] + off), "r"(hu) : "memory");
            d_hcat[((size_t)b_own * 512 + l) * 256 + dir * 128 + (j >> 1)] = hu;
        }
        __syncthreads();
        if (tid == 0) {
#pragma unroll
            for (int r = 0; r < 4; r++)
                if (r != (int)rank)
                    asm volatile("mbarrier.arrive.release.cluster.shared::cluster.b64 _, [%0];"
                                 :: "r"(rb2[r]) : "memory");
        }
        // producer gx prefetch for next step (into wait-2 shadow)
        if (step < 511) {
            int ln = dir ? (510 - step) : (step + 1);
            gxp = gxb + (size_t)(ln * 128 + b0 + bE) * 512 + gxoff;
            ga_u = gxp[0];
            gb_u = gxp[4];
        }
        {
            unsigned ph = (unsigned)step & 1u;
            MBAR_WAIT(b2_l, ph);
        }
        buf ^= 1;
    }

    asm volatile("barrier.cluster.arrive.aligned;" ::: "memory");
    asm volatile("barrier.cluster.wait.aligned;" ::: "memory");
}

// ---------------- K3: emission = hcat(bf16) @ w_cls^T + b_cls (float2 wc loads) ----------------
__global__ void __launch_bounds__(256) k_emis(const float* __restrict__ wcls,
                                              const float* __restrict__ bcls) {
    __shared__ float wc[16 * 512];
    int tid = threadIdx.x;
    for (int i = tid; i < 16 * 512 / 4; i += 256)
        ((float4*)wc)[i] = ((const float4*)wcls)[i];
    __syncthreads();
    int m = blockIdx.x * 8 + (tid >> 5);
    int lane = tid & 31;
    float acc[16];
#pragma unroll
    for (int t = 0; t < 16; t++) acc[t] = 0.f;
    const unsigned* hp = d_hcat + (size_t)m * 256;
#pragma unroll
    for (int it = 0; it < 8; it++) {
        int m32 = it * 32 + lane;
        unsigned u = hp[m32];
        float h0 = bflo(u), h1 = bfhi(u);
#pragma unroll
        for (int t = 0; t < 16; t++) {
            float2 w2 = *(const float2*)(wc + t * 512 + 2 * m32);
            acc[t] += h0 * w2.x + h1 * w2.y;
        }
    }
#pragma unroll
    for (int t = 0; t < 16; t++)
#pragma unroll
        for (int off = 16; off; off >>= 1) acc[t] += __shfl_xor_sync(0xffffffffu, acc[t], off);
    if (lane < 16) {
        float v = acc[0];
#pragma unroll
        for (int t = 1; t < 16; t++) v = (lane == t) ? acc[t] : v;
        d_emission[(size_t)m * 16 + lane] = v + bcls[lane];
    }
}

// ---------------- K4: CRF golden + forward (split-half logsumexp) ----------------
__global__ void k_crf(const int* __restrict__ tag, const float* __restrict__ trans) {
    __shared__ float tr[256];
    int b = blockIdx.x, lane = threadIdx.x;
    for (int i = lane; i < 256; i += 32) tr[i] = trans[i];
    __syncwarp();
    int cur = lane & 15;
    int half = lane >> 4;                   // 0: states 0-7, 1: states 8-15
    int pbase = half * 8;
    float tcol[8];
#pragma unroll
    for (int p = 0; p < 8; p++) tcol[p] = tr[(pbase + p) * 16 + cur];
    const int* tg = tag + b * 512;
    int len = 0;
    for (int l2 = lane; l2 < 512; l2 += 32) len += (tg[l2] != 0);
#pragma unroll
    for (int off = 16; off; off >>= 1) len += __shfl_xor_sync(0xffffffffu, len, off);

    const float* em = d_emission + (size_t)b * 512 * 16;
    float gsum = 0.f;
    for (int l2 = lane; l2 < 512; l2 += 32)
        if (l2 < len) {
            int t = tg[l2];
            int pv = l2 ? tg[l2 - 1] : 14;       // START=14
            gsum += em[l2 * 16 + t] + tr[pv * 16 + t];
        }
#pragma unroll
    for (int off = 16; off; off >>= 1) gsum += __shfl_xor_sync(0xffffffffu, gsum, off);

    // score for state `cur` lives in lanes 0-15 AND duplicated in 16-31
    float score = em[cur] + tr[14 * 16 + cur];
    for (int t = 1; t < 512; t++) {
        float v[8];
#pragma unroll
        for (int p = 0; p < 8; p++)
            v[p] = __shfl_sync(0xffffffffu, score, pbase + p) + tcol[p];
        float m01 = fmaxf(v[0], v[1]), m23 = fmaxf(v[2], v[3]);
        float m45 = fmaxf(v[4], v[5]), m67 = fmaxf(v[6], v[7]);
        float mh = fmaxf(fmaxf(m01, m23), fmaxf(m45, m67));
        float e0 = __expf(v[0] - mh), e1 = __expf(v[1] - mh);
        float e2 = __expf(v[2] - mh), e3 = __expf(v[3] - mh);
        float e4 = __expf(v[4] - mh), e5 = __expf(v[5] - mh);
        float e6 = __expf(v[6] - mh), e7 = __expf(v[7] - mh);
        float sh = ((e0 + e1) + (e2 + e3)) + ((e4 + e5) + (e6 + e7));
        // combine halves: logsumexp merge across lane^16
        float mo = __shfl_xor_sync(0xffffffffu, mh, 16);
        float so = __shfl_xor_sync(0xffffffffu, sh, 16);
        float m = fmaxf(mh, mo);
        float s = sh * __expf(mh - m) + so * __expf(mo - m);
        float ns = em[t * 16 + cur] + m + __logf(s);
        score = (t < len) ? ns : score;
    }
    if (lane == 15) atomicAdd(&d_acc[0], (double)score);  // END=15
    if (lane == 0)  atomicAdd(&d_acc[1], (double)gsum);
}

__global__ void k_final(float* out) {
    out[0] = (float)((d_acc[0] - d_acc[1]) / 128.0);
}

// ---------------- launch ----------------
extern "C" void kernel_launch(void* const* d_in, const int* in_sizes, int n_in,
                              void* d_out, int out_size) {
    const int*   batch_data = (const int*)d_in[0];
    const int*   batch_tag  = (const int*)d_in[1];
    const float* emb        = (const float*)d_in[2];
    const float* w_ih_f     = (const float*)d_in[3];
    const float* w_hh_f     = (const float*)d_in[4];
    const float* b_f        = (const float*)d_in[5];
    const float* w_ih_b     = (const float*)d_in[6];
    const float* w_hh_b     = (const float*)d_in[7];
    const float* b_b        = (const float*)d_in[8];
    const float* w_cls      = (const float*)d_in[9];
    const float* b_cls      = (const float*)d_in[10];
    const float* transition = (const float*)d_in[11];

    cudaFuncSetAttribute(k_recur, cudaFuncAttributeMaxDynamicSharedMemorySize, SMEM_R);
    cudaFuncSetAttribute(k_gemm, cudaFuncAttributeMaxDynamicSharedMemorySize, GSM);

    k_prep<<<512, 256>>>(w_hh_f, w_hh_b, w_ih_f, w_ih_b);
    k_gather<<<8192, 256>>>(batch_data, emb);
    k_gemm<<<dim3(512, 16), 256, GSM>>>(b_f, b_b);
    k_recur<<<128, 512, SMEM_R>>>();
    k_emis<<<8192, 256>>>(w_cls, b_cls);
    k_crf<<<128, 32>>>(batch_tag, transition);
    k_final<<<1, 1>>>((float*)d_out);
}

// round 16
// speedup vs baseline: 1.1193x; 1.0657x over previous
#include <cuda_runtime.h>
#include <cuda_bf16.h>

typedef unsigned long long ull;

// ---------------- device scratch (no runtime allocation) ----------------
__device__ __nv_bfloat16 d_xb[(size_t)65536 * 256];  // gathered embeddings bf16 [m][256]
__device__ unsigned d_gx[(size_t)2 * 65536 * 512];   // input gate preacts bf16x2 [dir][m][512 pairs]
__device__ unsigned d_hcat[(size_t)128 * 512 * 256]; // bf16x2 [b][l][256 pairs] (hf|hb)
__device__ float d_emission[(size_t)65536 * 16];     // [b*512+l][16]
__device__ uint4 d_whh2[65536];                      // W_hh mma B fragments [dir][gate][w][kt][lane]
__device__ uint4 d_wih2[65536];                      // W_ih mma B fragments [dir][nt16][kt][lane]
__device__ double d_acc[2];                          // [all_path, golden]

// ---------------- helpers ----------------
__device__ __forceinline__ float bflo(unsigned w) { return __uint_as_float(w << 16); }
__device__ __forceinline__ float bfhi(unsigned w) { return __uint_as_float(w & 0xffff0000u); }
__device__ __forceinline__ float bfhalf(unsigned u, int hi) {
    return __uint_as_float(hi ? (u & 0xffff0000u) : (u << 16));
}
__device__ __forceinline__ float tanha(float x) {
    float r; asm("tanh.approx.f32 %0,%1;" : "=f"(r) : "f"(x)); return r;
}
__device__ __forceinline__ float sigt(float x) { return fmaf(tanha(0.5f * x), 0.5f, 0.5f); }

__device__ __forceinline__ unsigned smem_u32(const void* p) {
    unsigned a;
    asm("{ .reg .u64 t; cvta.to.shared.u64 t, %1; cvt.u32.u64 %0, t; }" : "=r"(a) : "l"(p));
    return a;
}
__device__ __forceinline__ unsigned mapa_u32(unsigned a, unsigned rank) {
    unsigned d; asm("mapa.shared::cluster.u32 %0,%1,%2;" : "=r"(d) : "r"(a), "r"(rank));
    return d;
}
__device__ __forceinline__ unsigned cvt_bf2(float hi, float lo) {
    unsigned u; asm("cvt.rn.bf16x2.f32 %0,%1,%2;" : "=r"(u) : "f"(hi), "f"(lo)); return u;
}

#define MMA_BF16(C, A, B0, B1)                                                          \
    asm volatile("mma.sync.aligned.m16n8k16.row.col.f32.bf16.bf16.f32 "                 \
                 "{%0,%1,%2,%3},{%4,%5,%6,%7},{%8,%9},{%0,%1,%2,%3};"                   \
                 : "+f"((C)[0]), "+f"((C)[1]), "+f"((C)[2]), "+f"((C)[3])               \
                 : "r"((A)[0]), "r"((A)[1]), "r"((A)[2]), "r"((A)[3]),                  \
                   "r"(B0), "r"(B1))
#define LDSM4(R, ADDR)                                                                  \
    asm volatile("ldmatrix.sync.aligned.m8n8.x4.shared.b16 {%0,%1,%2,%3},[%4];"         \
                 : "=r"((R)[0]), "=r"((R)[1]), "=r"((R)[2]), "=r"((R)[3]) : "r"(ADDR))

#define MBAR_WAIT(ADDR, PH)                                                             \
    do {                                                                                \
        unsigned done;                                                                  \
        asm volatile("{\n\t.reg .pred p;\n\t"                                           \
                     "mbarrier.try_wait.parity.acquire.cluster.shared::cta.b64 p, [%1], %2;\n\t" \
                     "selp.b32 %0, 1, 0, p;\n\t}"                                       \
                     : "=r"(done) : "r"(ADDR), "r"(PH) : "memory");                     \
        while (!done)                                                                   \
            asm volatile("{\n\t.reg .pred p;\n\t"                                       \
                         "mbarrier.try_wait.parity.acquire.cluster.shared::cta.b64 p, [%1], %2, 0x989680;\n\t" \
                         "selp.b32 %0, 1, 0, p;\n\t}"                                   \
                         : "=r"(done) : "r"(ADDR), "r"(PH) : "memory");                 \
    } while (0)

// ---------------- K0: prep (whh + wih fragments, zero acc) ----------------
__device__ __forceinline__ unsigned pkbf(const float* s, int n, int k) {
    unsigned short lo = __bfloat16_as_ushort(__float2bfloat16(s[n * 256 + k]));
    unsigned short hi = __bfloat16_as_ushort(__float2bfloat16(s[n * 256 + k + 1]));
    return ((unsigned)hi << 16) | (unsigned)lo;
}
__global__ void k_prep(const float* __restrict__ whf, const float* __restrict__ whb,
                       const float* __restrict__ wif, const float* __restrict__ wib) {
    int e = blockIdx.x * 256 + threadIdx.x;   // 0..131071
    if (e < 65536) {
        int lane = e & 31, kt = (e >> 5) & 15, w = (e >> 9) & 15;
        int g = (e >> 13) & 3, dir = (e >> 15) & 1;
        const float* src = dir ? whb : whf;
        int row = g * 256 + w * 16 + (lane >> 2);
        int k0 = kt * 16 + (lane & 3) * 2;
        uint4 v;
        v.x = pkbf(src, row, k0);     v.y = pkbf(src, row, k0 + 8);
        v.z = pkbf(src, row + 8, k0); v.w = pkbf(src, row + 8, k0 + 8);
        d_whh2[e] = v;
    } else {
        int f = e - 65536;
        int lane = f & 31, kt = (f >> 5) & 15, nt = (f >> 9) & 63, dir = (f >> 15) & 1;
        const float* src = dir ? wib : wif;
        int row = nt * 16 + (lane >> 2);
        int k0 = kt * 16 + (lane & 3) * 2;
        uint4 v;
        v.x = pkbf(src, row, k0);     v.y = pkbf(src, row, k0 + 8);
        v.z = pkbf(src, row + 8, k0); v.w = pkbf(src, row + 8, k0 + 8);
        d_wih2[f] = v;
    }
    if (e < 2) d_acc[e] = 0.0;
}

// ---------------- K1a: embedding gather (fp32 -> bf16) ----------------
__global__ void k_gather(const int* __restrict__ bd, const float* __restrict__ emb) {
    int m = blockIdx.x * 8 + (threadIdx.x >> 5);
    int lane = threadIdx.x & 31;
    int b = m & 127, l = m >> 7;
    int idx = bd[b * 512 + l];
    const float* src = emb + (size_t)idx * 256;
    unsigned* dst = (unsigned*)(d_xb + (size_t)m * 256);
#pragma unroll
    for (int t = 0; t < 4; t++) {
        int i = lane + t * 32;
        float2 v = *(const float2*)(src + 2 * i);
        dst[i] = cvt_bf2(v.y, v.x);
    }
}

// ---------------- K1b: input projection, two-stage B smem staging ----------------
#define GSM 100352
__global__ void __launch_bounds__(256, 2) k_gemm(const float* __restrict__ bf_,
                                                 const float* __restrict__ bb_) {
    extern __shared__ char sm[];
    uint4* Bs = (uint4*)(sm + 67584);     // 2048 uint4 = 32 KB staging buffer
    int tid = threadIdx.x, lane = tid & 31, w = tid >> 5;
    int m0 = blockIdx.x * 128;
    int n0 = blockIdx.y * 128;
    int dir = n0 >> 10, nloc = n0 & 1023;

    // stage A tile 128 x 256 bf16 (pitch 528B -> conflict-free ldmatrix)
    for (int i = tid; i < 4096; i += 256) {
        int r = i >> 5, c = i & 31;
        ((uint4*)(sm + r * 528))[c] = ((const uint4*)(d_xb + (size_t)(m0 + r) * 256))[c];
    }

    const uint4* Bg = d_wih2 + ((size_t)dir * 64 + (nloc >> 4)) * 512;
    float c[16][4];
#pragma unroll
    for (int t = 0; t < 16; t++)
#pragma unroll
        for (int r = 0; r < 4; r++) c[t][r] = 0.f;

    unsigned ab = smem_u32(sm) + (unsigned)(w * 16 + (lane & 15)) * 528 + ((unsigned)(lane >> 4) << 4);

#pragma unroll
    for (int half = 0; half < 2; half++) {
        if (half) __syncthreads();        // prior-half mma reads done before overwrite
        for (int i = tid; i < 2048; i += 256) Bs[i] = Bg[half * 2048 + i];
        __syncthreads();
#pragma unroll
        for (int kt = 0; kt < 16; kt++) {
            unsigned a[4];
            LDSM4(a, ab + (unsigned)kt * 32);
#pragma unroll
            for (int p = 0; p < 4; p++) {
                uint4 bq = Bs[p * 512 + kt * 32 + lane];
                int t = (half * 4 + p) * 2;
                MMA_BF16(c[t], a, bq.x, bq.y);
                MMA_BF16(c[t + 1], a, bq.z, bq.w);
            }
        }
    }
    const float* Bv = dir ? bb_ : bf_;
    int mrow = m0 + w * 16 + (lane >> 2);
    unsigned* gbase = d_gx + ((size_t)dir * 65536 + mrow) * 512 + (nloc >> 1) + (lane & 3);
#pragma unroll
    for (int nt = 0; nt < 16; nt++) {
        float2 bv = *(const float2*)(Bv + nloc + nt * 8 + (lane & 3) * 2);
        gbase[nt * 4] = cvt_bf2(c[nt][1] + bv.y, c[nt][0] + bv.x);
        gbase[8 * 512 + nt * 4] = cvt_bf2(c[nt][3] + bv.y, c[nt][2] + bv.x);
    }
}

// ---------------- K2: LSTM recurrence, cluster-of-4 gate-split (R12 = best) ----------------
#define HPITCH   528
#define HBUFB    8448
#define OFF_H    0                       // h bufs [0, 16896)
#define OFF_RECV 16896                   // 4 KB: [gate][q][128 pairs]
#define OFF_MBAR 20992
#define SMEM_R   21008

__global__ void __launch_bounds__(512, 1) __cluster_dims__(4, 1, 1) k_recur() {
    extern __shared__ char sm[];
    int tid = threadIdx.x;
    unsigned rank;
    asm("mov.u32 %0, %%cluster_ctarank;" : "=r"(rank));
    int cid = blockIdx.x >> 2;
    int dir = cid >> 4;
    int b0 = (cid & 15) * 8;
    int lane = tid & 31, w = tid >> 5;

    // this warp's weight fragments (16 kt x uint4) -> registers, once
    const uint4* wgp = d_whh2 + (size_t)(dir * 4 + (int)rank) * 8192 + w * 512 + lane;
    uint4 wreg[16];
#pragma unroll
    for (int kt = 0; kt < 16; kt++) wreg[kt] = wgp[kt * 32];

    for (int i = tid; i < 2 * HBUFB / 4; i += 512) ((unsigned*)(sm + OFF_H))[i] = 0u;

    ull* mbar = (ull*)(sm + OFF_MBAR);
    if (tid == 0) {
        asm volatile("mbarrier.init.shared.b64 [%0], 3;" :: "r"(smem_u32(&mbar[0])) : "memory");
        asm volatile("mbarrier.init.shared.b64 [%0], 3;" :: "r"(smem_u32(&mbar[1])) : "memory");
    }
    __syncthreads();
    asm volatile("barrier.cluster.arrive.aligned;" ::: "memory");
    asm volatile("barrier.cluster.wait.aligned;" ::: "memory");

    unsigned rv_l = smem_u32(sm + OFF_RECV);
    unsigned h_l  = smem_u32(sm + OFF_H);
    unsigned b1_l = smem_u32(&mbar[0]);
    unsigned b2_l = smem_u32(&mbar[1]);
    unsigned rh[4], rb1[4], rb2[4];
#pragma unroll
    for (int r = 0; r < 4; r++) {
        rh[r]  = mapa_u32(h_l, r);
        rb1[r] = mapa_u32(b1_l, r);
        rb2[r] = mapa_u32(b2_l, r);
    }

    // producer roles: this CTA computes gate `rank` for 8 batch rows
    unsigned abase0 = h_l + (unsigned)(lane & 15) * HPITCH + ((unsigned)(lane >> 4) << 4);
    int bE = lane >> 2;
    unsigned rdst = (unsigned)(bE >> 1);
    int qE = bE & 1;
    int nl = w * 16 + (lane & 3) * 2;
    unsigned dst0 = mapa_u32(rv_l, rdst) + ((unsigned)rank * 256 + qE * 128 + (nl >> 1)) * 4;

    // consumer roles: cell update for own 2 batch rows
    int q = tid >> 8, j = tid & 255;
    int b_own = b0 + (int)rank * 2 + q;
    int hrow = (int)rank * 2 + q;
    const unsigned* rcv = (const unsigned*)(sm + OFF_RECV) + q * 128 + (j >> 1);
    int hlf = j & 1;

    float cc = 0.f;
    const unsigned* gxb = d_gx + (size_t)dir * 65536 * 512;
    int buf = 0;

    // producer gx prefetch (gate `rank` slice for batch bE), bf16x2 pairs
    int gxoff = (int)rank * 128 + (nl >> 1);
    int l0 = dir ? 511 : 0;
    const unsigned* gxp = gxb + (size_t)(l0 * 128 + b0 + bE) * 512 + gxoff;
    unsigned ga_u = gxp[0], gb_u = gxp[4];

    for (int step = 0; step < 512; step++) {
        int l = dir ? (511 - step) : step;

        // ---- matvec: this gate's 256 preacts for 8 batches (weights in regs) ----
        float c0[4] = {0.f, 0.f, 0.f, 0.f}, c1[4] = {0.f, 0.f, 0.f, 0.f};
        unsigned ab = abase0 + (unsigned)buf * HBUFB;
#pragma unroll
        for (int kt = 0; kt < 16; kt++) {
            unsigned a[4];
            LDSM4(a, ab + (unsigned)kt * 32);
            MMA_BF16(c0, a, wreg[kt].x, wreg[kt].y);
            MMA_BF16(c1, a, wreg[kt].z, wreg[kt].w);
        }
        // ship complete preacts (matvec + gx) to owner CTA
        unsigned u0 = cvt_bf2(c0[1] + bfhi(ga_u), c0[0] + bflo(ga_u));
        unsigned u1 = cvt_bf2(c1[1] + bfhi(gb_u), c1[0] + bflo(gb_u));
        asm volatile("st.shared::cluster.u32 [%0],%1;" :: "r"(dst0), "r"(u0) : "memory");
        asm volatile("st.shared::cluster.u32 [%0],%1;" :: "r"(dst0 + 16), "r"(u1) : "memory");
        __syncthreads();
        if (tid == 0) {
#pragma unroll
            for (int r = 0; r < 4; r++)
                if (r != (int)rank)
                    asm volatile("mbarrier.arrive.release.cluster.shared::cluster.b64 _, [%0];"
                                 :: "r"(rb1[r]) : "memory");
        }
        {
            unsigned ph = (unsigned)step & 1u;
            MBAR_WAIT(b1_l, ph);
        }

        // ---- cell update for own 2 batch rows (preacts already include gx) ----
        float pi = bfhalf(rcv[0],   hlf);
        float pf = bfhalf(rcv[256], hlf);
        float pg = bfhalf(rcv[512], hlf);
        float po = bfhalf(rcv[768], hlf);
        float i_ = sigt(pi), f_ = sigt(pf), g_ = tanha(pg), o_ = sigt(po);
        cc = f_ * cc + i_ * g_;
        float hv = o_ * tanha(cc);

        // ---- broadcast new h row to all 4 CTAs + bf16x2 hcat store ----
        float hn = __shfl_down_sync(0xffffffffu, hv, 1);
        if (!hlf) {
            unsigned hu = cvt_bf2(hn, hv);
            unsigned off = (unsigned)(buf ^ 1) * HBUFB + (unsigned)hrow * HPITCH + (unsigned)j * 2;
#pragma unroll
            for (int r = 0; r < 4; r++)
                asm volatile("st.shared::cluster.u32 [%0],%1;" :: "r"(rh[r] + off), "r"(hu) : "memory");
            d_hcat[((size_t)b_own * 512 + l) * 256 + dir * 128 + (j >> 1)] = hu;
        }
        __syncthreads();
        if (tid == 0) {
#pragma unroll
            for (int r = 0; r < 4; r++)
                if (r != (int)rank)
                    asm volatile("mbarrier.arrive.release.cluster.shared::cluster.b64 _, [%0];"
                                 :: "r"(rb2[r]) : "memory");
        }
        // producer gx prefetch for next step (into wait-2 shadow)
        if (step < 511) {
            int ln = dir ? (510 - step) : (step + 1);
            gxp = gxb + (size_t)(ln * 128 + b0 + bE) * 512 + gxoff;
            ga_u = gxp[0];
            gb_u = gxp[4];
        }
        {
            unsigned ph = (unsigned)step & 1u;
            MBAR_WAIT(b2_l, ph);
        }
        buf ^= 1;
    }

    asm volatile("barrier.cluster.arrive.aligned;" ::: "memory");
    asm volatile("barrier.cluster.wait.aligned;" ::: "memory");
}

// ---------------- K3: emission = hcat(bf16) @ w_cls^T + b_cls (float2 wc loads) ----------------
__global__ void __launch_bounds__(256) k_emis(const float* __restrict__ wcls,
                                              const float* __restrict__ bcls) {
    __shared__ float wc[16 * 512];
    int tid = threadIdx.x;
    for (int i = tid; i < 16 * 512 / 4; i += 256)
        ((float4*)wc)[i] = ((const float4*)wcls)[i];
    __syncthreads();
    int m = blockIdx.x * 8 + (tid >> 5);
    int lane = tid & 31;
    float acc[16];
#pragma unroll
    for (int t = 0; t < 16; t++) acc[t] = 0.f;
    const unsigned* hp = d_hcat + (size_t)m * 256;
#pragma unroll
    for (int it = 0; it < 8; it++) {
        int m32 = it * 32 + lane;
        unsigned u = hp[m32];
        float h0 = bflo(u), h1 = bfhi(u);
#pragma unroll
        for (int t = 0; t < 16; t++) {
            float2 w2 = *(const float2*)(wc + t * 512 + 2 * m32);
            acc[t] += h0 * w2.x + h1 * w2.y;
        }
    }
#pragma unroll
    for (int t = 0; t < 16; t++)
#pragma unroll
        for (int off = 16; off; off >>= 1) acc[t] += __shfl_xor_sync(0xffffffffu, acc[t], off);
    if (lane < 16) {
        float v = acc[0];
#pragma unroll
        for (int t = 1; t < 16; t++) v = (lane == t) ? acc[t] : v;
        d_emission[(size_t)m * 16 + lane] = v + bcls[lane];
    }
}

// ---------------- K4: CRF golden + forward (split-half logsumexp) ----------------
__global__ void k_crf(const int* __restrict__ tag, const float* __restrict__ trans) {
    __shared__ float tr[256];
    int b = blockIdx.x, lane = threadIdx.x;
    for (int i = lane; i < 256; i += 32) tr[i] = trans[i];
    __syncwarp();
    int cur = lane & 15;
    int half = lane >> 4;                   // 0: states 0-7, 1: states 8-15
    int pbase = half * 8;
    float tcol[8];
#pragma unroll
    for (int p = 0; p < 8; p++) tcol[p] = tr[(pbase + p) * 16 + cur];
    const int* tg = tag + b * 512;
    int len = 0;
    for (int l2 = lane; l2 < 512; l2 += 32) len += (tg[l2] != 0);
#pragma unroll
    for (int off = 16; off; off >>= 1) len += __shfl_xor_sync(0xffffffffu, len, off);

    const float* em = d_emission + (size_t)b * 512 * 16;
    float gsum = 0.f;
    for (int l2 = lane; l2 < 512; l2 += 32)
        if (l2 < len) {
            int t = tg[l2];
            int pv = l2 ? tg[l2 - 1] : 14;       // START=14
            gsum += em[l2 * 16 + t] + tr[pv * 16 + t];
        }
#pragma unroll
    for (int off = 16; off; off >>= 1) gsum += __shfl_xor_sync(0xffffffffu, gsum, off);

    float score = em[cur] + tr[14 * 16 + cur];
    for (int t = 1; t < 512; t++) {
        float v[8];
#pragma unroll
        for (int p = 0; p < 8; p++)
            v[p] = __shfl_sync(0xffffffffu, score, pbase + p) + tcol[p];
        float m01 = fmaxf(v[0], v[1]), m23 = fmaxf(v[2], v[3]);
        float m45 = fmaxf(v[4], v[5]), m67 = fmaxf(v[6], v[7]);
        float mh = fmaxf(fmaxf(m01, m23), fmaxf(m45, m67));
        float e0 = __expf(v[0] - mh), e1 = __expf(v[1] - mh);
        float e2 = __expf(v[2] - mh), e3 = __expf(v[3] - mh);
        float e4 = __expf(v[4] - mh), e5 = __expf(v[5] - mh);
        float e6 = __expf(v[6] - mh), e7 = __expf(v[7] - mh);
        float sh = ((e0 + e1) + (e2 + e3)) + ((e4 + e5) + (e6 + e7));
        float mo = __shfl_xor_sync(0xffffffffu, mh, 16);
        float so = __shfl_xor_sync(0xffffffffu, sh, 16);
        float m = fmaxf(mh, mo);
        float s = sh * __expf(mh - m) + so * __expf(mo - m);
        float ns = em[t * 16 + cur] + m + __logf(s);
        score = (t < len) ? ns : score;
    }
    if (lane == 15) atomicAdd(&d_acc[0], (double)score);  // END=15
    if (lane == 0)  atomicAdd(&d_acc[1], (double)gsum);
}

__global__ void k_final(float* out) {
    out[0] = (float)((d_acc[0] - d_acc[1]) / 128.0);
}

// ---------------- launch ----------------
extern "C" void kernel_launch(void* const* d_in, const int* in_sizes, int n_in,
                              void* d_out, int out_size) {
    const int*   batch_data = (const int*)d_in[0];
    const int*   batch_tag  = (const int*)d_in[1];
    const float* emb        = (const float*)d_in[2];
    const float* w_ih_f     = (const float*)d_in[3];
    const float* w_hh_f     = (const float*)d_in[4];
    const float* b_f        = (const float*)d_in[5];
    const float* w_ih_b     = (const float*)d_in[6];
    const float* w_hh_b     = (const float*)d_in[7];
    const float* b_b        = (const float*)d_in[8];
    const float* w_cls      = (const float*)d_in[9];
    const float* b_cls      = (const float*)d_in[10];
    const float* transition = (const float*)d_in[11];

    cudaFuncSetAttribute(k_recur, cudaFuncAttributeMaxDynamicSharedMemorySize, SMEM_R);
    cudaFuncSetAttribute(k_gemm, cudaFuncAttributeMaxDynamicSharedMemorySize, GSM);

    k_prep<<<512, 256>>>(w_hh_f, w_hh_b, w_ih_f, w_ih_b);
    k_gather<<<8192, 256>>>(batch_data, emb);
    k_gemm<<<dim3(512, 16), 256, GSM>>>(b_f, b_b);
    k_recur<<<128, 512, SMEM_R>>>();
    k_emis<<<8192, 256>>>(w_cls, b_cls);
    k_crf<<<128, 32>>>(batch_tag, transition);
    k_final<<<1, 1>>>((float*)d_out);
}

// round 17
// speedup vs baseline: 1.3247x; 1.1835x over previous
#include <cuda_runtime.h>
#include <cuda_bf16.h>

typedef unsigned long long ull;

// ---------------- device scratch (no runtime allocation) ----------------
__device__ __nv_bfloat16 d_xb[(size_t)65536 * 256];  // gathered embeddings bf16 [m][256]
__device__ unsigned d_gx[(size_t)2 * 65536 * 512];   // input gate preacts bf16x2 [dir][m][512 pairs]
__device__ unsigned d_hcat[(size_t)128 * 512 * 256]; // bf16x2 [b][l][256 pairs] (hf|hb)
__device__ float d_emission[(size_t)65536 * 16];     // [b*512+l][16]
__device__ uint4 d_whh2[65536];                      // W_hh mma B fragments [dir][gate][w][kt][lane]
__device__ uint4 d_wih2[65536];                      // W_ih mma B fragments [dir][nt16][kt][lane]
__device__ double d_acc[2];                          // [all_path, golden]

// ---------------- helpers ----------------
__device__ __forceinline__ float bflo(unsigned w) { return __uint_as_float(w << 16); }
__device__ __forceinline__ float bfhi(unsigned w) { return __uint_as_float(w & 0xffff0000u); }
__device__ __forceinline__ float bfhalf(unsigned u, int hi) {
    return __uint_as_float(hi ? (u & 0xffff0000u) : (u << 16));
}
__device__ __forceinline__ float tanha(float x) {
    float r; asm("tanh.approx.f32 %0,%1;" : "=f"(r) : "f"(x)); return r;
}
__device__ __forceinline__ float sigt(float x) { return fmaf(tanha(0.5f * x), 0.5f, 0.5f); }

__device__ __forceinline__ unsigned smem_u32(const void* p) {
    unsigned a;
    asm("{ .reg .u64 t; cvta.to.shared.u64 t, %1; cvt.u32.u64 %0, t; }" : "=r"(a) : "l"(p));
    return a;
}
__device__ __forceinline__ unsigned mapa_u32(unsigned a, unsigned rank) {
    unsigned d; asm("mapa.shared::cluster.u32 %0,%1,%2;" : "=r"(d) : "r"(a), "r"(rank));
    return d;
}
__device__ __forceinline__ unsigned cvt_bf2(float hi, float lo) {
    unsigned u; asm("cvt.rn.bf16x2.f32 %0,%1,%2;" : "=r"(u) : "f"(hi), "f"(lo)); return u;
}

#define MMA_BF16(C, A, B0, B1)                                                          \
    asm volatile("mma.sync.aligned.m16n8k16.row.col.f32.bf16.bf16.f32 "                 \
                 "{%0,%1,%2,%3},{%4,%5,%6,%7},{%8,%9},{%0,%1,%2,%3};"                   \
                 : "+f"((C)[0]), "+f"((C)[1]), "+f"((C)[2]), "+f"((C)[3])               \
                 : "r"((A)[0]), "r"((A)[1]), "r"((A)[2]), "r"((A)[3]),                  \
                   "r"(B0), "r"(B1))
#define LDSM4(R, ADDR)                                                                  \
    asm volatile("ldmatrix.sync.aligned.m8n8.x4.shared.b16 {%0,%1,%2,%3},[%4];"         \
                 : "=r"((R)[0]), "=r"((R)[1]), "=r"((R)[2]), "=r"((R)[3]) : "r"(ADDR))

#define MBAR_WAIT(ADDR, PH)                                                             \
    do {                                                                                \
        unsigned done;                                                                  \
        asm volatile("{\n\t.reg .pred p;\n\t"                                           \
                     "mbarrier.try_wait.parity.acquire.cluster.shared::cta.b64 p, [%1], %2;\n\t" \
                     "selp.b32 %0, 1, 0, p;\n\t}"                                       \
                     : "=r"(done) : "r"(ADDR), "r"(PH) : "memory");                     \
        while (!done)                                                                   \
            asm volatile("{\n\t.reg .pred p;\n\t"                                       \
                         "mbarrier.try_wait.parity.acquire.cluster.shared::cta.b64 p, [%1], %2, 0x989680;\n\t" \
                         "selp.b32 %0, 1, 0, p;\n\t}"                                   \
                         : "=r"(done) : "r"(ADDR), "r"(PH) : "memory");                 \
    } while (0)

// ---------------- K0: prep (whh + wih fragments, zero acc) ----------------
__device__ __forceinline__ unsigned pkbf(const float* s, int n, int k) {
    unsigned short lo = __bfloat16_as_ushort(__float2bfloat16(s[n * 256 + k]));
    unsigned short hi = __bfloat16_as_ushort(__float2bfloat16(s[n * 256 + k + 1]));
    return ((unsigned)hi << 16) | (unsigned)lo;
}
__global__ void k_prep(const float* __restrict__ whf, const float* __restrict__ whb,
                       const float* __restrict__ wif, const float* __restrict__ wib) {
    int e = blockIdx.x * 256 + threadIdx.x;   // 0..131071
    if (e < 65536) {
        int lane = e & 31, kt = (e >> 5) & 15, w = (e >> 9) & 15;
        int g = (e >> 13) & 3, dir = (e >> 15) & 1;
        const float* src = dir ? whb : whf;
        int row = g * 256 + w * 16 + (lane >> 2);
        int k0 = kt * 16 + (lane & 3) * 2;
        uint4 v;
        v.x = pkbf(src, row, k0);     v.y = pkbf(src, row, k0 + 8);
        v.z = pkbf(src, row + 8, k0); v.w = pkbf(src, row + 8, k0 + 8);
        d_whh2[e] = v;
    } else {
        int f = e - 65536;
        int lane = f & 31, kt = (f >> 5) & 15, nt = (f >> 9) & 63, dir = (f >> 15) & 1;
        const float* src = dir ? wib : wif;
        int row = nt * 16 + (lane >> 2);
        int k0 = kt * 16 + (lane & 3) * 2;
        uint4 v;
        v.x = pkbf(src, row, k0);     v.y = pkbf(src, row, k0 + 8);
        v.z = pkbf(src, row + 8, k0); v.w = pkbf(src, row + 8, k0 + 8);
        d_wih2[f] = v;
    }
    if (e < 2) d_acc[e] = 0.0;
}

// ---------------- K1a: embedding gather (fp32 -> bf16) ----------------
__global__ void k_gather(const int* __restrict__ bd, const float* __restrict__ emb) {
    int m = blockIdx.x * 8 + (threadIdx.x >> 5);
    int lane = threadIdx.x & 31;
    int b = m & 127, l = m >> 7;
    int idx = bd[b * 512 + l];
    const float* src = emb + (size_t)idx * 256;
    unsigned* dst = (unsigned*)(d_xb + (size_t)m * 256);
#pragma unroll
    for (int t = 0; t < 4; t++) {
        int i = lane + t * 32;
        float2 v = *(const float2*)(src + 2 * i);
        dst[i] = cvt_bf2(v.y, v.x);
    }
}

// ---------------- K1b: input projection, two-stage B staging + coalesced epilogue ----------------
#define GSM 102400
__global__ void __launch_bounds__(256, 2) k_gemm(const float* __restrict__ bf_,
                                                 const float* __restrict__ bb_) {
    extern __shared__ char sm[];
    uint4* Bs = (uint4*)(sm + 67584);     // 32 KB B staging; reused as 34 KB output staging
    unsigned* Os = (unsigned*)(sm + 67584);
    int tid = threadIdx.x, lane = tid & 31, w = tid >> 5;
    int m0 = blockIdx.x * 128;
    int n0 = blockIdx.y * 128;
    int dir = n0 >> 10, nloc = n0 & 1023;

    // stage A tile 128 x 256 bf16 (pitch 528B -> conflict-free ldmatrix)
    for (int i = tid; i < 4096; i += 256) {
        int r = i >> 5, c = i & 31;
        ((uint4*)(sm + r * 528))[c] = ((const uint4*)(d_xb + (size_t)(m0 + r) * 256))[c];
    }

    const uint4* Bg = d_wih2 + ((size_t)dir * 64 + (nloc >> 4)) * 512;
    float c[16][4];
#pragma unroll
    for (int t = 0; t < 16; t++)
#pragma unroll
        for (int r = 0; r < 4; r++) c[t][r] = 0.f;

    unsigned ab = smem_u32(sm) + (unsigned)(w * 16 + (lane & 15)) * 528 + ((unsigned)(lane >> 4) << 4);

#pragma unroll
    for (int half = 0; half < 2; half++) {
        if (half) __syncthreads();        // prior-half mma reads done before overwrite
        for (int i = tid; i < 2048; i += 256) Bs[i] = Bg[half * 2048 + i];
        __syncthreads();
#pragma unroll
        for (int kt = 0; kt < 16; kt++) {
            unsigned a[4];
            LDSM4(a, ab + (unsigned)kt * 32);
#pragma unroll
            for (int p = 0; p < 4; p++) {
                uint4 bq = Bs[p * 512 + kt * 32 + lane];
                int t = (half * 4 + p) * 2;
                MMA_BF16(c[t], a, bq.x, bq.y);
                MMA_BF16(c[t + 1], a, bq.z, bq.w);
            }
        }
    }
    // ---- epilogue: stage bf16x2 output tile in smem (pitch 68 -> conflict-free), then coalesce ----
    __syncthreads();                      // all mma reads of Bs done before overwrite
    const float* Bv = dir ? bb_ : bf_;
    int rl = w * 16 + (lane >> 2);        // local row 0..127 (and +8)
#pragma unroll
    for (int nt = 0; nt < 16; nt++) {
        float2 bv = *(const float2*)(Bv + nloc + nt * 8 + (lane & 3) * 2);
        int cidx = nt * 4 + (lane & 3);
        Os[rl * 68 + cidx]       = cvt_bf2(c[nt][1] + bv.y, c[nt][0] + bv.x);
        Os[(rl + 8) * 68 + cidx] = cvt_bf2(c[nt][3] + bv.y, c[nt][2] + bv.x);
    }
    __syncthreads();
    unsigned* gout = d_gx + (size_t)dir * 65536 * 512 + (size_t)m0 * 512 + (nloc >> 1);
    for (int i = tid; i < 2048; i += 256) {
        int r = i >> 4, cidx = i & 15;
        uint4 v = *(const uint4*)(Os + r * 68 + cidx * 4);
        *(uint4*)(gout + (size_t)r * 512 + cidx * 4) = v;
    }
}

// ---------------- K2: LSTM recurrence, cluster-of-4 gate-split (R12 protocol, parallel arrives) ----------------
#define HPITCH   528
#define HBUFB    8448
#define OFF_H    0                       // h bufs [0, 16896)
#define OFF_RECV 16896                   // 4 KB: [gate][q][128 pairs]
#define OFF_MBAR 20992
#define SMEM_R   21008

__global__ void __launch_bounds__(512, 1) __cluster_dims__(4, 1, 1) k_recur() {
    extern __shared__ char sm[];
    int tid = threadIdx.x;
    unsigned rank;
    asm("mov.u32 %0, %%cluster_ctarank;" : "=r"(rank));
    int cid = blockIdx.x >> 2;
    int dir = cid >> 4;
    int b0 = (cid & 15) * 8;
    int lane = tid & 31, w = tid >> 5;

    // this warp's weight fragments (16 kt x uint4) -> registers, once
    const uint4* wgp = d_whh2 + (size_t)(dir * 4 + (int)rank) * 8192 + w * 512 + lane;
    uint4 wreg[16];
#pragma unroll
    for (int kt = 0; kt < 16; kt++) wreg[kt] = wgp[kt * 32];

    for (int i = tid; i < 2 * HBUFB / 4; i += 512) ((unsigned*)(sm + OFF_H))[i] = 0u;

    ull* mbar = (ull*)(sm + OFF_MBAR);
    if (tid == 0) {
        asm volatile("mbarrier.init.shared.b64 [%0], 3;" :: "r"(smem_u32(&mbar[0])) : "memory");
        asm volatile("mbarrier.init.shared.b64 [%0], 3;" :: "r"(smem_u32(&mbar[1])) : "memory");
    }
    __syncthreads();
    asm volatile("barrier.cluster.arrive.aligned;" ::: "memory");
    asm volatile("barrier.cluster.wait.aligned;" ::: "memory");

    unsigned rv_l = smem_u32(sm + OFF_RECV);
    unsigned h_l  = smem_u32(sm + OFF_H);
    unsigned b1_l = smem_u32(&mbar[0]);
    unsigned b2_l = smem_u32(&mbar[1]);
    unsigned rh[4];
#pragma unroll
    for (int r = 0; r < 4; r++) rh[r] = mapa_u32(h_l, r);
    // parallel-arrive targets: thread t (<4, != rank) arrives at CTA t's barriers
    int arr_on = (tid < 4) && (tid != (int)rank);
    unsigned t1 = 0, t2 = 0;
    if (tid < 4) { t1 = mapa_u32(b1_l, (unsigned)tid); t2 = mapa_u32(b2_l, (unsigned)tid); }

    // producer roles: this CTA computes gate `rank` for 8 batch rows
    unsigned abase0 = h_l + (unsigned)(lane & 15) * HPITCH + ((unsigned)(lane >> 4) << 4);
    int bE = lane >> 2;
    unsigned rdst = (unsigned)(bE >> 1);
    int qE = bE & 1;
    int nl = w * 16 + (lane & 3) * 2;
    unsigned dst0 = mapa_u32(rv_l, rdst) + ((unsigned)rank * 256 + qE * 128 + (nl >> 1)) * 4;

    // consumer roles: cell update for own 2 batch rows
    int q = tid >> 8, j = tid & 255;
    int b_own = b0 + (int)rank * 2 + q;
    int hrow = (int)rank * 2 + q;
    const unsigned* rcv = (const unsigned*)(sm + OFF_RECV) + q * 128 + (j >> 1);
    int hlf = j & 1;

    float cc = 0.f;
    const unsigned* gxb = d_gx + (size_t)dir * 65536 * 512;
    int buf = 0;

    // producer gx prefetch (gate `rank` slice for batch bE), bf16x2 pairs
    int gxoff = (int)rank * 128 + (nl >> 1);
    int l0 = dir ? 511 : 0;
    const unsigned* gxp = gxb + (size_t)(l0 * 128 + b0 + bE) * 512 + gxoff;
    unsigned ga_u = gxp[0], gb_u = gxp[4];

    for (int step = 0; step < 512; step++) {
        int l = dir ? (511 - step) : step;

        // ---- matvec: this gate's 256 preacts for 8 batches (weights in regs) ----
        float c0[4] = {0.f, 0.f, 0.f, 0.f}, c1[4] = {0.f, 0.f, 0.f, 0.f};
        unsigned ab = abase0 + (unsigned)buf * HBUFB;
#pragma unroll
        for (int kt = 0; kt < 16; kt++) {
            unsigned a[4];
            LDSM4(a, ab + (unsigned)kt * 32);
            MMA_BF16(c0, a, wreg[kt].x, wreg[kt].y);
            MMA_BF16(c1, a, wreg[kt].z, wreg[kt].w);
        }
        // ship complete preacts (matvec + gx) to owner CTA
        unsigned u0 = cvt_bf2(c0[1] + bfhi(ga_u), c0[0] + bflo(ga_u));
        unsigned u1 = cvt_bf2(c1[1] + bfhi(gb_u), c1[0] + bflo(gb_u));
        asm volatile("st.shared::cluster.u32 [%0],%1;" :: "r"(dst0), "r"(u0) : "memory");
        asm volatile("st.shared::cluster.u32 [%0],%1;" :: "r"(dst0 + 16), "r"(u1) : "memory");
        __syncthreads();
        if (arr_on)
            asm volatile("mbarrier.arrive.release.cluster.shared::cluster.b64 _, [%0];"
                         :: "r"(t1) : "memory");
        {
            unsigned ph = (unsigned)step & 1u;
            MBAR_WAIT(b1_l, ph);
        }

        // ---- cell update for own 2 batch rows (preacts already include gx) ----
        float pi = bfhalf(rcv[0],   hlf);
        float pf = bfhalf(rcv[256], hlf);
        float pg = bfhalf(rcv[512], hlf);
        float po = bfhalf(rcv[768], hlf);
        float i_ = sigt(pi), f_ = sigt(pf), g_ = tanha(pg), o_ = sigt(po);
        cc = f_ * cc + i_ * g_;
        float hv = o_ * tanha(cc);

        // ---- broadcast new h row to all 4 CTAs + bf16x2 hcat store ----
        float hn = __shfl_down_sync(0xffffffffu, hv, 1);
        if (!hlf) {
            unsigned hu = cvt_bf2(hn, hv);
            unsigned off = (unsigned)(buf ^ 1) * HBUFB + (unsigned)hrow * HPITCH + (unsigned)j * 2;
#pragma unroll
            for (int r = 0; r < 4; r++)
                asm volatile("st.shared::cluster.u32 [%0],%1;" :: "r"(rh[r] + off), "r"(hu) : "memory");
            d_hcat[((size_t)b_own * 512 + l) * 256 + dir * 128 + (j >> 1)] = hu;
        }
        __syncthreads();
        if (arr_on)
            asm volatile("mbarrier.arrive.release.cluster.shared::cluster.b64 _, [%0];"
                         :: "r"(t2) : "memory");
        // producer gx prefetch for next step (into wait-2 shadow)
        if (step < 511) {
            int ln = dir ? (510 - step) : (step + 1);
            gxp = gxb + (size_t)(ln * 128 + b0 + bE) * 512 + gxoff;
            ga_u = gxp[0];
            gb_u = gxp[4];
        }
        {
            unsigned ph = (unsigned)step & 1u;
            MBAR_WAIT(b2_l, ph);
        }
        buf ^= 1;
    }

    asm volatile("barrier.cluster.arrive.aligned;" ::: "memory");
    asm volatile("barrier.cluster.wait.aligned;" ::: "memory");
}

// ---------------- K3: emission = hcat(bf16) @ w_cls^T + b_cls (float2 wc loads) ----------------
__global__ void __launch_bounds__(256) k_emis(const float* __restrict__ wcls,
                                              const float* __restrict__ bcls) {
    __shared__ float wc[16 * 512];
    int tid = threadIdx.x;
    for (int i = tid; i < 16 * 512 / 4; i += 256)
        ((float4*)wc)[i] = ((const float4*)wcls)[i];
    __syncthreads();
    int m = blockIdx.x * 8 + (tid >> 5);
    int lane = tid & 31;
    float acc[16];
#pragma unroll
    for (int t = 0; t < 16; t++) acc[t] = 0.f;
    const unsigned* hp = d_hcat + (size_t)m * 256;
#pragma unroll
    for (int it = 0; it < 8; it++) {
        int m32 = it * 32 + lane;
        unsigned u = hp[m32];
        float h0 = bflo(u), h1 = bfhi(u);
#pragma unroll
        for (int t = 0; t < 16; t++) {
            float2 w2 = *(const float2*)(wc + t * 512 + 2 * m32);
            acc[t] += h0 * w2.x + h1 * w2.y;
        }
    }
#pragma unroll
    for (int t = 0; t < 16; t++)
#pragma unroll
        for (int off = 16; off; off >>= 1) acc[t] += __shfl_xor_sync(0xffffffffu, acc[t], off);
    if (lane < 16) {
        float v = acc[0];
#pragma unroll
        for (int t = 1; t < 16; t++) v = (lane == t) ? acc[t] : v;
        d_emission[(size_t)m * 16 + lane] = v + bcls[lane];
    }
}

// ---------------- K4: CRF golden + forward (split-half logsumexp) ----------------
__global__ void k_crf(const int* __restrict__ tag, const float* __restrict__ trans) {
    __shared__ float tr[256];
    int b = blockIdx.x, lane = threadIdx.x;
    for (int i = lane; i < 256; i += 32) tr[i] = trans[i];
    __syncwarp();
    int cur = lane & 15;
    int half = lane >> 4;                   // 0: states 0-7, 1: states 8-15
    int pbase = half * 8;
    float tcol[8];
#pragma unroll
    for (int p = 0; p < 8; p++) tcol[p] = tr[(pbase + p) * 16 + cur];
    const int* tg = tag + b * 512;
    int len = 0;
    for (int l2 = lane; l2 < 512; l2 += 32) len += (tg[l2] != 0);
#pragma unroll
    for (int off = 16; off; off >>= 1) len += __shfl_xor_sync(0xffffffffu, len, off);

    const float* em = d_emission + (size_t)b * 512 * 16;
    float gsum = 0.f;
    for (int l2 = lane; l2 < 512; l2 += 32)
        if (l2 < len) {
            int t = tg[l2];
            int pv = l2 ? tg[l2 - 1] : 14;       // START=14
            gsum += em[l2 * 16 + t] + tr[pv * 16 + t];
        }
#pragma unroll
    for (int off = 16; off; off >>= 1) gsum += __shfl_xor_sync(0xffffffffu, gsum, off);

    float score = em[cur] + tr[14 * 16 + cur];
    for (int t = 1; t < 512; t++) {
        float v[8];
#pragma unroll
        for (int p = 0; p < 8; p++)
            v[p] = __shfl_sync(0xffffffffu, score, pbase + p) + tcol[p];
        float m01 = fmaxf(v[0], v[1]), m23 = fmaxf(v[2], v[3]);
        float m45 = fmaxf(v[4], v[5]), m67 = fmaxf(v[6], v[7]);
        float mh = fmaxf(fmaxf(m01, m23), fmaxf(m45, m67));
        float e0 = __expf(v[0] - mh), e1 = __expf(v[1] - mh);
        float e2 = __expf(v[2] - mh), e3 = __expf(v[3] - mh);
        float e4 = __expf(v[4] - mh), e5 = __expf(v[5] - mh);
        float e6 = __expf(v[6] - mh), e7 = __expf(v[7] - mh);
        float sh = ((e0 + e1) + (e2 + e3)) + ((e4 + e5) + (e6 + e7));
        float mo = __shfl_xor_sync(0xffffffffu, mh, 16);
        float so = __shfl_xor_sync(0xffffffffu, sh, 16);
        float m = fmaxf(mh, mo);
        float s = sh * __expf(mh - m) + so * __expf(mo - m);
        float ns = em[t * 16 + cur] + m + __logf(s);
        score = (t < len) ? ns : score;
    }
    if (lane == 15) atomicAdd(&d_acc[0], (double)score);  // END=15
    if (lane == 0)  atomicAdd(&d_acc[1], (double)gsum);
}

__global__ void k_final(float* out) {
    out[0] = (float)((d_acc[0] - d_acc[1]) / 128.0);
}

// ---------------- launch ----------------
extern "C" void kernel_launch(void* const* d_in, const int* in_sizes, int n_in,
                              void* d_out, int out_size) {
    const int*   batch_data = (const int*)d_in[0];
    const int*   batch_tag  = (const int*)d_in[1];
    const float* emb        = (const float*)d_in[2];
    const float* w_ih_f     = (const float*)d_in[3];
    const float* w_hh_f     = (const float*)d_in[4];
    const float* b_f        = (const float*)d_in[5];
    const float* w_ih_b     = (const float*)d_in[6];
    const float* w_hh_b     = (const float*)d_in[7];
    const float* b_b        = (const float*)d_in[8];
    const float* w_cls      = (const float*)d_in[9];
    const float* b_cls      = (const float*)d_in[10];
    const float* transition = (const float*)d_in[11];

    cudaFuncSetAttribute(k_recur, cudaFuncAttributeMaxDynamicSharedMemorySize, SMEM_R);
    cudaFuncSetAttribute(k_gemm, cudaFuncAttributeMaxDynamicSharedMemorySize, GSM);

    k_prep<<<512, 256>>>(w_hh_f, w_hh_b, w_ih_f, w_ih_b);
    k_gather<<<8192, 256>>>(batch_data, emb);
    k_gemm<<<dim3(512, 16), 256, GSM>>>(b_f, b_b);
    k_recur<<<128, 512, SMEM_R>>>();
    k_emis<<<8192, 256>>>(w_cls, b_cls);
    k_crf<<<128, 32>>>(batch_tag, transition);
    k_final<<<1, 1>>>((float*)d_out);
}